// round 1
// baseline (speedup 1.0000x reference)
#include <cuda_runtime.h>
#include <cuda_bf16.h>

#define BINS 64
#define ROWS 96                 // B*C = 32*3
#define HW   262144             // 512*512
#define BLOCKS_PER_ROW 16
#define THREADS 256
#define WARPS (THREADS / 32)

// Signed diff histogram scratch: fake counts minus real counts, per (b,c) row.
__device__ int g_diff[ROWS * BINS];

__device__ __forceinline__ int bin_of(float x) {
    // clip to [0,1]; *64 is exact (power-of-two scale); trunc == astype(int32); clip to 63
    x = fminf(fmaxf(x, 0.0f), 1.0f);
    int i = (int)(x * 64.0f);
    return i > 63 ? 63 : i;
}

__global__ void zero_kernel() {
    int i = blockIdx.x * blockDim.x + threadIdx.x;
    if (i < ROWS * BINS) g_diff[i] = 0;
}

__global__ __launch_bounds__(THREADS) void hist_kernel(
    const float4* __restrict__ fake, const float4* __restrict__ real_)
{
    __shared__ int sh[WARPS][BINS];
    const int tid  = threadIdx.x;
    const int warp = tid >> 5;

    #pragma unroll
    for (int i = tid; i < WARPS * BINS; i += THREADS)
        ((int*)sh)[i] = 0;
    __syncthreads();

    const int row = blockIdx.x / BLOCKS_PER_ROW;
    const int seg = blockIdx.x % BLOCKS_PER_ROW;
    const int vec_per_row = HW / 4;                       // 65536 float4
    const int vec_per_seg = vec_per_row / BLOCKS_PER_ROW; // 4096 float4
    const long base = (long)row * vec_per_row + (long)seg * vec_per_seg;

    for (int i = tid; i < vec_per_seg; i += THREADS) {
        float4 f = fake[base + i];
        float4 r = real_[base + i];
        atomicAdd(&sh[warp][bin_of(f.x)], 1);
        atomicAdd(&sh[warp][bin_of(f.y)], 1);
        atomicAdd(&sh[warp][bin_of(f.z)], 1);
        atomicAdd(&sh[warp][bin_of(f.w)], 1);
        atomicAdd(&sh[warp][bin_of(r.x)], -1);
        atomicAdd(&sh[warp][bin_of(r.y)], -1);
        atomicAdd(&sh[warp][bin_of(r.z)], -1);
        atomicAdd(&sh[warp][bin_of(r.w)], -1);
    }
    __syncthreads();

    // Reduce the per-warp hists, one global atomic per bin per block.
    for (int b = tid; b < BINS; b += THREADS) {
        int s = 0;
        #pragma unroll
        for (int w = 0; w < WARPS; w++) s += sh[w][b];
        if (s != 0) atomicAdd(&g_diff[row * BINS + b], s);
    }
}

__global__ __launch_bounds__(256) void reduce_kernel(float* __restrict__ out) {
    __shared__ int warp_sums[8];
    const int tid = threadIdx.x;

    // Max possible |diff| total = 2 * ROWS * HW = 50,331,648 < 2^31, int is safe.
    int s = 0;
    for (int i = tid; i < ROWS * BINS; i += 256) {
        int v = g_diff[i];
        s += (v < 0) ? -v : v;
    }
    #pragma unroll
    for (int off = 16; off > 0; off >>= 1)
        s += __shfl_down_sync(0xFFFFFFFFu, s, off);
    if ((tid & 31) == 0) warp_sums[tid >> 5] = s;
    __syncthreads();
    if (tid == 0) {
        int total = 0;
        #pragma unroll
        for (int w = 0; w < 8; w++) total += warp_sums[w];
        // loss = total / (HW * ROWS * BINS)
        out[0] = (float)((double)total / ((double)HW * (double)(ROWS * BINS)));
    }
}

extern "C" void kernel_launch(void* const* d_in, const int* in_sizes, int n_in,
                              void* d_out, int out_size) {
    const float4* fake  = (const float4*)d_in[0];
    const float4* real_ = (const float4*)d_in[1];
    float* out = (float*)d_out;

    zero_kernel<<<(ROWS * BINS + 255) / 256, 256>>>();
    hist_kernel<<<ROWS * BLOCKS_PER_ROW, THREADS>>>(fake, real_);
    reduce_kernel<<<1, 256>>>(out);
}